// round 7
// baseline (speedup 1.0000x reference)
#include <cuda_runtime.h>

// Detail loss, simplified:
//   D = sum_c (infer - ref)   per image plane
//   out = (sum|D[w+1]-D[w-1]| + sum|D[h+1]-D[h-1]|) * 0.25 / (98*258*256)
// Warp-per-row-strip, no smem/barriers, and a one-row-ahead software pipeline:
// raw loads for row g+2 are issued before row g+1 is combined/consumed, so each
// warp keeps ~24 LDG.128 in flight instead of 12.

#define NIMG   98            // 2*7*7
#define IMG_H  256
#define IMG_W  256
#define RSTRIP 16            // rows per warp strip
#define STRIPS (IMG_H / RSTRIP)        // 16
#define NBLK   (NIMG * STRIPS)         // 1568 one-warp blocks
#define PLANE  (IMG_H * IMG_W)

__device__ float        g_partials[NBLK];
__device__ unsigned int g_count;     // zero-init; reset each launch by last block

struct Raw {
    float4 a[6];   // infer: 3 channels x 2 float4
    float4 b[6];   // ref
};

__device__ __forceinline__ void issue_load(const float* __restrict__ pi,
                                           const float* __restrict__ pr,
                                           int row, int lane, bool valid, Raw& r) {
    if (valid) {
        const size_t off = (size_t)row * IMG_W + lane * 8;
        #pragma unroll
        for (int c = 0; c < 3; c++) {
            const float* a = pi + (size_t)c * PLANE + off;
            const float* b = pr + (size_t)c * PLANE + off;
            r.a[c * 2]     = __ldcs((const float4*)a);
            r.a[c * 2 + 1] = __ldcs((const float4*)(a + 4));
            r.b[c * 2]     = __ldcs((const float4*)b);
            r.b[c * 2 + 1] = __ldcs((const float4*)(b + 4));
        }
    } else {
        const float4 z = make_float4(0.f, 0.f, 0.f, 0.f);
        #pragma unroll
        for (int i = 0; i < 6; i++) { r.a[i] = z; r.b[i] = z; }
    }
}

__device__ __forceinline__ void combine(const Raw& r, float d[8]) {
    #pragma unroll
    for (int j = 0; j < 8; j++) d[j] = 0.f;
    #pragma unroll
    for (int c = 0; c < 3; c++) {
        const float4 a0 = r.a[c * 2], a1 = r.a[c * 2 + 1];
        const float4 b0 = r.b[c * 2], b1 = r.b[c * 2 + 1];
        d[0] += a0.x - b0.x;  d[1] += a0.y - b0.y;
        d[2] += a0.z - b0.z;  d[3] += a0.w - b0.w;
        d[4] += a1.x - b1.x;  d[5] += a1.y - b1.y;
        d[6] += a1.z - b1.z;  d[7] += a1.w - b1.w;
    }
}

__global__ void __launch_bounds__(32)
detail_kernel(const float* __restrict__ infer, const float* __restrict__ ref,
              float* __restrict__ out) {
    const int blk   = blockIdx.x;
    const int n     = blk / STRIPS;
    const int strip = blk % STRIPS;
    const int r0    = strip * RSTRIP;
    const int lane  = threadIdx.x;

    const float* pi = infer + (size_t)n * 3 * PLANE;
    const float* pr = ref   + (size_t)n * 3 * PLANE;

    // Prologue: rows r0-1, r0 (combined immediately), row r0+1 in flight.
    Raw buf[2];
    Raw rtop, rcur;
    issue_load(pi, pr, r0 - 1, lane, r0 > 0, rtop);
    issue_load(pi, pr, r0,     lane, true,   rcur);
    issue_load(pi, pr, r0 + 1, lane, true,   buf[1]);   // consumed at h=0

    float pm[8], pc[8], pn[8];
    combine(rtop, pm);
    combine(rcur, pc);

    float sum_h = 0.f, sum_v = 0.f;

    #pragma unroll 2
    for (int h = 0; h < RSTRIP; h++) {
        const int g = r0 + h;
        // Issue loads for row g+2 BEFORE consuming row g+1 (one-ahead pipeline).
        issue_load(pi, pr, g + 2, lane, (g + 2) < IMG_H && h + 1 < RSTRIP, buf[h & 1]);

        combine(buf[(h + 1) & 1], pn);   // row g+1, issued last iteration

        // Horizontal gradient on row g (values in pc).
        float left  = __shfl_up_sync(0xffffffffu,  pc[7], 1);
        float right = __shfl_down_sync(0xffffffffu, pc[0], 1);
        if (lane == 0)  left  = 0.f;
        if (lane == 31) right = 0.f;
        sum_h += fabsf(pc[1] - left);
        #pragma unroll
        for (int j = 1; j < 7; j++) sum_h += fabsf(pc[j + 1] - pc[j - 1]);
        sum_h += fabsf(right - pc[6]);

        // Vertical gradient on row g.
        #pragma unroll
        for (int j = 0; j < 8; j++) sum_v += fabsf(pn[j] - pm[j]);

        // Roll the window.
        #pragma unroll
        for (int j = 0; j < 8; j++) { pm[j] = pc[j]; pc[j] = pn[j]; }
    }

    // Warp reduction.
    float s = sum_h + sum_v;
    #pragma unroll
    for (int off = 16; off > 0; off >>= 1)
        s += __shfl_down_sync(0xffffffffu, s, off);

    int last = 0;
    if (lane == 0) {
        g_partials[blk] = s;
        __threadfence();
        last = (atomicAdd(&g_count, 1u) == NBLK - 1);
    }
    last = __shfl_sync(0xffffffffu, last, 0);

    if (last) {
        float t = 0.f;
        for (int i = lane; i < NBLK; i += 32)
            t += __ldcg(&g_partials[i]);
        #pragma unroll
        for (int off = 16; off > 0; off >>= 1)
            t += __shfl_down_sync(0xffffffffu, t, off);
        if (lane == 0) {
            // 0.5 (gradient coeff) * 0.5 (avg of two losses) / (98*258*256)
            out[0] = t * (0.25f / 6472704.0f);
            g_count = 0;   // deterministic across graph replays
        }
    }
}

extern "C" void kernel_launch(void* const* d_in, const int* in_sizes, int n_in,
                              void* d_out, int out_size) {
    const float* infer = (const float*)d_in[0];
    const float* ref   = (const float*)d_in[1];
    detail_kernel<<<NBLK, 32>>>(infer, ref, (float*)d_out);
}

// round 8
// speedup vs baseline: 1.0077x; 1.0077x over previous
#include <cuda_runtime.h>

// Detail loss, simplified:
//   D = sum_c (infer - ref)   per image plane
//   out = (sum|D[w+1]-D[w-1]| + sum|D[h+1]-D[h-1]|) * 0.25 / (98*258*256)
// Warp-per-row-strip, no smem/barriers in the hot loop, one-row-ahead pipeline.
// RSTRIP=8 -> 3136 warps (21/SM) so aggregate MLP saturates DRAM even if
// ptxas partially serializes per-warp loads. Default (non-streaming) loads so
// halo rows hit L2.

#define NIMG   98            // 2*7*7
#define IMG_H  256
#define IMG_W  256
#define RSTRIP 8             // rows per warp strip
#define STRIPS (IMG_H / RSTRIP)          // 32
#define NWARPS (NIMG * STRIPS)           // 3136
#define WPB    4
#define NBLOCKS (NWARPS / WPB)           // 784
#define PLANE  (IMG_H * IMG_W)

__device__ float        g_partials[NWARPS];
__device__ unsigned int g_count;     // zero-init; reset each launch by last block

struct Raw {
    float4 a[6];   // infer: 3 channels x 2 float4
    float4 b[6];   // ref
};

__device__ __forceinline__ void issue_load(const float* __restrict__ pi,
                                           const float* __restrict__ pr,
                                           int row, int lane, bool valid, Raw& r) {
    if (valid) {
        const size_t off = (size_t)row * IMG_W + lane * 8;
        #pragma unroll
        for (int c = 0; c < 3; c++) {
            const float* a = pi + (size_t)c * PLANE + off;
            const float* b = pr + (size_t)c * PLANE + off;
            r.a[c * 2]     = *(const float4*)a;
            r.a[c * 2 + 1] = *(const float4*)(a + 4);
            r.b[c * 2]     = *(const float4*)b;
            r.b[c * 2 + 1] = *(const float4*)(b + 4);
        }
    } else {
        const float4 z = make_float4(0.f, 0.f, 0.f, 0.f);
        #pragma unroll
        for (int i = 0; i < 6; i++) { r.a[i] = z; r.b[i] = z; }
    }
}

__device__ __forceinline__ void combine(const Raw& r, float d[8]) {
    #pragma unroll
    for (int j = 0; j < 8; j++) d[j] = 0.f;
    #pragma unroll
    for (int c = 0; c < 3; c++) {
        const float4 a0 = r.a[c * 2], a1 = r.a[c * 2 + 1];
        const float4 b0 = r.b[c * 2], b1 = r.b[c * 2 + 1];
        d[0] += a0.x - b0.x;  d[1] += a0.y - b0.y;
        d[2] += a0.z - b0.z;  d[3] += a0.w - b0.w;
        d[4] += a1.x - b1.x;  d[5] += a1.y - b1.y;
        d[6] += a1.z - b1.z;  d[7] += a1.w - b1.w;
    }
}

__global__ void __launch_bounds__(WPB * 32)
detail_kernel(const float* __restrict__ infer, const float* __restrict__ ref,
              float* __restrict__ out) {
    const int tid   = threadIdx.x;
    const int lane  = tid & 31;
    const int gw    = blockIdx.x * WPB + (tid >> 5);   // global warp id
    const int n     = gw / STRIPS;
    const int strip = gw % STRIPS;
    const int r0    = strip * RSTRIP;

    const float* pi = infer + (size_t)n * 3 * PLANE;
    const float* pr = ref   + (size_t)n * 3 * PLANE;

    // Prologue: rows r0-1, r0 combined immediately; row r0+1 left in flight.
    Raw buf[2];
    Raw rtop, rcur;
    issue_load(pi, pr, r0 - 1, lane, r0 > 0, rtop);
    issue_load(pi, pr, r0,     lane, true,   rcur);
    issue_load(pi, pr, r0 + 1, lane, true,   buf[1]);   // consumed at h=0

    float pm[8], pc[8], pn[8];
    combine(rtop, pm);
    combine(rcur, pc);

    float sum_h = 0.f, sum_v = 0.f;

    #pragma unroll 2
    for (int h = 0; h < RSTRIP; h++) {
        const int g = r0 + h;
        // Issue loads for row g+2 BEFORE consuming row g+1 (one-ahead pipeline).
        issue_load(pi, pr, g + 2, lane, (g + 2) < IMG_H && h + 1 < RSTRIP, buf[h & 1]);

        combine(buf[(h + 1) & 1], pn);   // row g+1, issued last iteration

        // Horizontal gradient on row g (values in pc).
        float left  = __shfl_up_sync(0xffffffffu,  pc[7], 1);
        float right = __shfl_down_sync(0xffffffffu, pc[0], 1);
        if (lane == 0)  left  = 0.f;
        if (lane == 31) right = 0.f;
        sum_h += fabsf(pc[1] - left);
        #pragma unroll
        for (int j = 1; j < 7; j++) sum_h += fabsf(pc[j + 1] - pc[j - 1]);
        sum_h += fabsf(right - pc[6]);

        // Vertical gradient on row g.
        #pragma unroll
        for (int j = 0; j < 8; j++) sum_v += fabsf(pn[j] - pm[j]);

        // Roll the window.
        #pragma unroll
        for (int j = 0; j < 8; j++) { pm[j] = pc[j]; pc[j] = pn[j]; }
    }

    // Warp reduction.
    float s = sum_h + sum_v;
    #pragma unroll
    for (int off = 16; off > 0; off >>= 1)
        s += __shfl_down_sync(0xffffffffu, s, off);

    __shared__ bool is_last;
    if (lane == 0) {
        g_partials[gw] = s;
        __threadfence();            // make this warp's partial globally visible
    }
    __syncthreads();
    if (tid == 0)
        is_last = (atomicAdd(&g_count, 1u) == NBLOCKS - 1);
    __syncthreads();

    if (is_last) {
        float t = 0.f;
        for (int i = tid; i < NWARPS; i += WPB * 32)
            t += __ldcg(&g_partials[i]);
        #pragma unroll
        for (int off = 16; off > 0; off >>= 1)
            t += __shfl_down_sync(0xffffffffu, t, off);
        __shared__ float wsum[WPB];
        if (lane == 0) wsum[tid >> 5] = t;
        __syncthreads();
        if (tid == 0) {
            float u = 0.f;
            #pragma unroll
            for (int i = 0; i < WPB; i++) u += wsum[i];
            // 0.5 (gradient coeff) * 0.5 (avg of two losses) / (98*258*256)
            out[0] = u * (0.25f / 6472704.0f);
            g_count = 0;   // deterministic across graph replays
        }
    }
}

extern "C" void kernel_launch(void* const* d_in, const int* in_sizes, int n_in,
                              void* d_out, int out_size) {
    const float* infer = (const float*)d_in[0];
    const float* ref   = (const float*)d_in[1];
    detail_kernel<<<NBLOCKS, WPB * 32>>>(infer, ref, (float*)d_out);
}